// round 3
// baseline (speedup 1.0000x reference)
#include <cuda_runtime.h>

// Problem constants
#define Dd   512
#define Ss   1024
#define Bb   8
#define Vv   32000
#define MT   (Bb * Ss)          // 8192 tokens
#define EPSF 1e-5f

// Scratch (allocation-free rule: __device__ globals)
__device__ float g_f [MT * Dd];   // sigmoid gate
__device__ float g_a1[MT * Dd];   // W1 branch -> becomes xmix
__device__ float g_a2[MT * Dd];   // W2 branch
__device__ float g_xf[MT * Dd];   // final-LN'd scan output

// GEMM tiling
#define BM 128
#define BN 128
#define BK 16
#define TM 8
#define TN 8
#define PAD 4

__device__ __forceinline__ float sigmoidf_(float x) {
    return 1.0f / (1.0f + __expf(-x));
}

// ---------------------------------------------------------------------------
// C[m][n] = act( sum_k E[tokens[m]][k] * W[k][n] + bias[n] )
// MODE 0: identity, MODE 1: sigmoid. M=8192, N=K=512.
// ---------------------------------------------------------------------------
template <int MODE>
__global__ __launch_bounds__(256) void gemm_embed_k(
    const int*   __restrict__ tokens,
    const float* __restrict__ E,
    const float* __restrict__ W,
    const float* __restrict__ bias,
    float*       __restrict__ C)
{
    __shared__ float As[BK][BM + PAD];
    __shared__ float Bs[BK][BN + PAD];

    const int tid = threadIdx.x;
    const int m0  = blockIdx.y * BM;
    const int n0  = blockIdx.x * BN;

    // A-tile loaders: 128 rows x 16 k, float4 along k, transposed store
    const int rA = tid >> 2;          // 0..63 (+64 second pass)
    const int cA = (tid & 3) << 2;    // 0,4,8,12
    // B-tile loaders: 16 k-rows x 128 n, direct float4 store
    const int rB = tid >> 5;          // 0..7 (+8 second pass)
    const int cB = (tid & 31) << 2;   // 0..124

    const int tr = (tid >> 4) << 3;   // 0..120
    const int tc = (tid & 15) << 3;   // 0..120

    const int tok0 = tokens[m0 + rA];
    const int tok1 = tokens[m0 + rA + 64];
    const float* arow0 = E + (size_t)tok0 * Dd;
    const float* arow1 = E + (size_t)tok1 * Dd;

    float acc[TM][TN] = {};

    for (int k0 = 0; k0 < Dd; k0 += BK) {
        float4 a0 = *reinterpret_cast<const float4*>(arow0 + k0 + cA);
        float4 a1 = *reinterpret_cast<const float4*>(arow1 + k0 + cA);
        As[cA + 0][rA]      = a0.x;
        As[cA + 1][rA]      = a0.y;
        As[cA + 2][rA]      = a0.z;
        As[cA + 3][rA]      = a0.w;
        As[cA + 0][rA + 64] = a1.x;
        As[cA + 1][rA + 64] = a1.y;
        As[cA + 2][rA + 64] = a1.z;
        As[cA + 3][rA + 64] = a1.w;

        float4 b0 = *reinterpret_cast<const float4*>(W + (size_t)(k0 + rB)     * Dd + n0 + cB);
        float4 b1 = *reinterpret_cast<const float4*>(W + (size_t)(k0 + rB + 8) * Dd + n0 + cB);
        *reinterpret_cast<float4*>(&Bs[rB][cB])     = b0;
        *reinterpret_cast<float4*>(&Bs[rB + 8][cB]) = b1;

        __syncthreads();

        #pragma unroll
        for (int k = 0; k < BK; k++) {
            float regM[TM], regN[TN];
            *reinterpret_cast<float4*>(&regM[0]) = *reinterpret_cast<const float4*>(&As[k][tr]);
            *reinterpret_cast<float4*>(&regM[4]) = *reinterpret_cast<const float4*>(&As[k][tr + 4]);
            *reinterpret_cast<float4*>(&regN[0]) = *reinterpret_cast<const float4*>(&Bs[k][tc]);
            *reinterpret_cast<float4*>(&regN[4]) = *reinterpret_cast<const float4*>(&Bs[k][tc + 4]);
            #pragma unroll
            for (int i = 0; i < TM; i++)
                #pragma unroll
                for (int j = 0; j < TN; j++)
                    acc[i][j] = fmaf(regM[i], regN[j], acc[i][j]);
        }
        __syncthreads();
    }

    #pragma unroll
    for (int i = 0; i < TM; i++) {
        float* crow = C + (size_t)(m0 + tr + i) * Dd + n0 + tc;
        #pragma unroll
        for (int j = 0; j < TN; j++) {
            float v = acc[i][j] + bias[n0 + tc + j];
            if (MODE == 1) v = sigmoidf_(v);
            crow[j] = v;
        }
    }
}

// ---------------------------------------------------------------------------
// Logits: C[m][n] = sum_k X[m][k] * E[n][k]   (NT). M=8192, N=32000, K=512.
// Double-buffered smem pipeline: prefetch slab k+1 while computing slab k.
// ---------------------------------------------------------------------------
__global__ __launch_bounds__(256) void gemm_logits_k(
    const float* __restrict__ X,
    const float* __restrict__ E,
    float*       __restrict__ C)
{
    __shared__ float As[2][BK][BM + PAD];
    __shared__ float Bs[2][BK][BN + PAD];

    const int tid = threadIdx.x;
    const int m0  = blockIdx.y * BM;
    const int n0  = blockIdx.x * BN;

    const int rA = tid >> 2;          // 0..63 (+64)
    const int cA = (tid & 3) << 2;    // 0,4,8,12

    const int tr = (tid >> 4) << 3;
    const int tc = (tid & 15) << 3;

    const float* arow0 = X + (size_t)(m0 + rA)      * Dd + cA;
    const float* arow1 = X + (size_t)(m0 + rA + 64) * Dd + cA;
    const float* brow0 = E + (size_t)(n0 + rA)      * Dd + cA;
    const float* brow1 = E + (size_t)(n0 + rA + 64) * Dd + cA;

    float acc[TM][TN] = {};

    // Preload slab 0 into buffer 0
    {
        float4 a0 = *reinterpret_cast<const float4*>(arow0);
        float4 a1 = *reinterpret_cast<const float4*>(arow1);
        float4 b0 = *reinterpret_cast<const float4*>(brow0);
        float4 b1 = *reinterpret_cast<const float4*>(brow1);
        As[0][cA + 0][rA]      = a0.x;
        As[0][cA + 1][rA]      = a0.y;
        As[0][cA + 2][rA]      = a0.z;
        As[0][cA + 3][rA]      = a0.w;
        As[0][cA + 0][rA + 64] = a1.x;
        As[0][cA + 1][rA + 64] = a1.y;
        As[0][cA + 2][rA + 64] = a1.z;
        As[0][cA + 3][rA + 64] = a1.w;
        Bs[0][cA + 0][rA]      = b0.x;
        Bs[0][cA + 1][rA]      = b0.y;
        Bs[0][cA + 2][rA]      = b0.z;
        Bs[0][cA + 3][rA]      = b0.w;
        Bs[0][cA + 0][rA + 64] = b1.x;
        Bs[0][cA + 1][rA + 64] = b1.y;
        Bs[0][cA + 2][rA + 64] = b1.z;
        Bs[0][cA + 3][rA + 64] = b1.w;
    }
    __syncthreads();

    const int NSLAB = Dd / BK;   // 32
    #pragma unroll 1
    for (int t = 0; t < NSLAB; t++) {
        const int cur = t & 1;
        const int nxt = cur ^ 1;
        const bool has_next = (t + 1 < NSLAB);

        // Prefetch next slab into registers (issues LDGs early; latency
        // overlapped with the FFMA block below).
        float4 pa0, pa1, pb0, pb1;
        if (has_next) {
            const int ko = (t + 1) * BK;
            pa0 = *reinterpret_cast<const float4*>(arow0 + ko);
            pa1 = *reinterpret_cast<const float4*>(arow1 + ko);
            pb0 = *reinterpret_cast<const float4*>(brow0 + ko);
            pb1 = *reinterpret_cast<const float4*>(brow1 + ko);
        }

        #pragma unroll
        for (int k = 0; k < BK; k++) {
            float regM[TM], regN[TN];
            *reinterpret_cast<float4*>(&regM[0]) = *reinterpret_cast<const float4*>(&As[cur][k][tr]);
            *reinterpret_cast<float4*>(&regM[4]) = *reinterpret_cast<const float4*>(&As[cur][k][tr + 4]);
            *reinterpret_cast<float4*>(&regN[0]) = *reinterpret_cast<const float4*>(&Bs[cur][k][tc]);
            *reinterpret_cast<float4*>(&regN[4]) = *reinterpret_cast<const float4*>(&Bs[cur][k][tc + 4]);
            #pragma unroll
            for (int i = 0; i < TM; i++)
                #pragma unroll
                for (int j = 0; j < TN; j++)
                    acc[i][j] = fmaf(regM[i], regN[j], acc[i][j]);
        }

        if (has_next) {
            As[nxt][cA + 0][rA]      = pa0.x;
            As[nxt][cA + 1][rA]      = pa0.y;
            As[nxt][cA + 2][rA]      = pa0.z;
            As[nxt][cA + 3][rA]      = pa0.w;
            As[nxt][cA + 0][rA + 64] = pa1.x;
            As[nxt][cA + 1][rA + 64] = pa1.y;
            As[nxt][cA + 2][rA + 64] = pa1.z;
            As[nxt][cA + 3][rA + 64] = pa1.w;
            Bs[nxt][cA + 0][rA]      = pb0.x;
            Bs[nxt][cA + 1][rA]      = pb0.y;
            Bs[nxt][cA + 2][rA]      = pb0.z;
            Bs[nxt][cA + 3][rA]      = pb0.w;
            Bs[nxt][cA + 0][rA + 64] = pb1.x;
            Bs[nxt][cA + 1][rA + 64] = pb1.y;
            Bs[nxt][cA + 2][rA + 64] = pb1.z;
            Bs[nxt][cA + 3][rA + 64] = pb1.w;
            __syncthreads();
        }
    }

    #pragma unroll
    for (int i = 0; i < TM; i++) {
        float* crow = C + (size_t)(m0 + tr + i) * Vv + n0 + tc;
        #pragma unroll
        for (int j = 0; j < TN; j += 4) {
            float4 v = make_float4(acc[i][j], acc[i][j + 1], acc[i][j + 2], acc[i][j + 3]);
            *reinterpret_cast<float4*>(crow + j) = v;
        }
    }
}

// ---------------------------------------------------------------------------
// xmix = silu(a1) * a2, written in place over a1.
// ---------------------------------------------------------------------------
__global__ void mix_k(float4* __restrict__ a1, const float4* __restrict__ a2, int n4)
{
    int i = blockIdx.x * blockDim.x + threadIdx.x;
    if (i < n4) {
        float4 x = a1[i];
        float4 y = a2[i];
        x.x = x.x * sigmoidf_(x.x) * y.x;
        x.y = x.y * sigmoidf_(x.y) * y.y;
        x.z = x.z * sigmoidf_(x.z) * y.z;
        x.w = x.w * sigmoidf_(x.w) * y.w;
        a1[i] = x;
    }
}

// ---------------------------------------------------------------------------
// Sequential scan + both layernorms fused. One block per batch row.
// 128 threads x float4 = D=512.
// ---------------------------------------------------------------------------
__device__ __forceinline__ void block_red2(float& a, float& b, float* red, int tid)
{
    #pragma unroll
    for (int off = 16; off > 0; off >>= 1) {
        a += __shfl_xor_sync(0xffffffffu, a, off);
        b += __shfl_xor_sync(0xffffffffu, b, off);
    }
    const int w = tid >> 5;
    if ((tid & 31) == 0) { red[w] = a; red[8 + w] = b; }
    __syncthreads();
    a = red[0] + red[1] + red[2] + red[3];
    b = red[8] + red[9] + red[10] + red[11];
    __syncthreads();
}

__global__ __launch_bounds__(128) void scan_k(
    const float* __restrict__ f,
    const float* __restrict__ x,
    const float* __restrict__ ln_g,  const float* __restrict__ ln_b,
    const float* __restrict__ h0,
    const float* __restrict__ lnf_g, const float* __restrict__ lnf_b,
    float*       __restrict__ xf)
{
    const int b   = blockIdx.x;
    const int tid = threadIdx.x;
    __shared__ float red[16];

    const float4* fp = reinterpret_cast<const float4*>(f  + (size_t)b * Ss * Dd);
    const float4* xp = reinterpret_cast<const float4*>(x  + (size_t)b * Ss * Dd);
    float4*       op = reinterpret_cast<float4*>      (xf + (size_t)b * Ss * Dd);

    const float4 g  = reinterpret_cast<const float4*>(ln_g)[tid];
    const float4 be = reinterpret_cast<const float4*>(ln_b)[tid];
    const float4 fg = reinterpret_cast<const float4*>(lnf_g)[tid];
    const float4 fb = reinterpret_cast<const float4*>(lnf_b)[tid];
    float4 h        = reinterpret_cast<const float4*>(h0)[tid];

    const float invD = 1.0f / (float)Dd;

    for (int s = 0; s < Ss; s++) {
        float4 ft = fp[s * 128 + tid];
        float4 xt = xp[s * 128 + tid];

        float4 hr;
        hr.x = ft.x * h.x + (1.0f - ft.x) * xt.x;
        hr.y = ft.y * h.y + (1.0f - ft.y) * xt.y;
        hr.z = ft.z * h.z + (1.0f - ft.z) * xt.z;
        hr.w = ft.w * h.w + (1.0f - ft.w) * xt.w;

        float sa = hr.x + hr.y + hr.z + hr.w;
        float sb = hr.x * hr.x + hr.y * hr.y + hr.z * hr.z + hr.w * hr.w;
        block_red2(sa, sb, red, tid);
        float mean = sa * invD;
        float var  = sb * invD - mean * mean;
        float rstd = rsqrtf(var + EPSF);

        float4 hn;
        hn.x = (hr.x - mean) * rstd * g.x + be.x + h.x;
        hn.y = (hr.y - mean) * rstd * g.y + be.y + h.y;
        hn.z = (hr.z - mean) * rstd * g.z + be.z + h.z;
        hn.w = (hr.w - mean) * rstd * g.w + be.w + h.w;
        h = hn;

        sa = hn.x + hn.y + hn.z + hn.w;
        sb = hn.x * hn.x + hn.y * hn.y + hn.z * hn.z + hn.w * hn.w;
        block_red2(sa, sb, red, tid);
        mean = sa * invD;
        var  = sb * invD - mean * mean;
        rstd = rsqrtf(var + EPSF);

        float4 o;
        o.x = (hn.x - mean) * rstd * fg.x + fb.x;
        o.y = (hn.y - mean) * rstd * fg.y + fb.y;
        o.z = (hn.z - mean) * rstd * fg.z + fb.z;
        o.w = (hn.w - mean) * rstd * fg.w + fb.w;
        op[s * 128 + tid] = o;
    }
}

// ---------------------------------------------------------------------------
extern "C" void kernel_launch(void* const* d_in, const int* in_sizes, int n_in,
                              void* d_out, int out_size)
{
    const int*   tokens = (const int*)  d_in[0];
    const float* E      = (const float*)d_in[1];
    const float* W_ih   = (const float*)d_in[2];
    const float* b_h    = (const float*)d_in[3];
    const float* W1     = (const float*)d_in[4];
    const float* b1     = (const float*)d_in[5];
    const float* W2     = (const float*)d_in[6];
    const float* b2     = (const float*)d_in[7];
    const float* ln_g   = (const float*)d_in[8];
    const float* ln_b   = (const float*)d_in[9];
    const float* h0     = (const float*)d_in[10];
    const float* lnf_g  = (const float*)d_in[11];
    const float* lnf_b  = (const float*)d_in[12];
    float* out          = (float*)d_out;

    float *fP, *a1P, *a2P, *xfP;
    cudaGetSymbolAddress((void**)&fP,  g_f);
    cudaGetSymbolAddress((void**)&a1P, g_a1);
    cudaGetSymbolAddress((void**)&a2P, g_a2);
    cudaGetSymbolAddress((void**)&xfP, g_xf);

    dim3 blk(256);
    dim3 grid_in(Dd / BN, MT / BM);       // (4, 64)
    gemm_embed_k<1><<<grid_in, blk>>>(tokens, E, W_ih, b_h, fP);
    gemm_embed_k<0><<<grid_in, blk>>>(tokens, E, W1,  b1,  a1P);
    gemm_embed_k<0><<<grid_in, blk>>>(tokens, E, W2,  b2,  a2P);

    const int n4 = MT * Dd / 4;
    mix_k<<<(n4 + 255) / 256, 256>>>((float4*)a1P, (const float4*)a2P, n4);

    scan_k<<<Bb, 128>>>(fP, a1P, ln_g, ln_b, h0, lnf_g, lnf_b, xfP);

    dim3 grid_lg(Vv / BN, MT / BM);       // (250, 64)
    gemm_logits_k<<<grid_lg, blk>>>(xfP, E, out);
}

// round 5
// speedup vs baseline: 2.3838x; 2.3838x over previous
#include <cuda_runtime.h>
#include <cstdint>

// Problem constants
#define Dd   512
#define Ss   1024
#define Bb   8
#define Vv   32000
#define MT   (Bb * Ss)          // 8192 tokens
#define EPSF 1e-5f

// Scratch (allocation-free rule: __device__ globals)
__device__ float g_f [MT * Dd];
__device__ float g_a1[MT * Dd];
__device__ float g_a2[MT * Dd];
__device__ float g_xf[MT * Dd];

__device__ __forceinline__ uint32_t smem_u32(const void* p) {
    uint32_t a;
    asm("{ .reg .u64 t; cvta.to.shared.u64 t, %1; cvt.u32.u64 %0, t; }" : "=r"(a) : "l"(p));
    return a;
}
__device__ __forceinline__ uint32_t f2tf32(float x) {
    uint32_t r;
    asm("cvt.rna.tf32.f32 %0, %1;" : "=r"(r) : "f"(x));
    return r;
}
__device__ __forceinline__ void mma_tf32(float* c, const uint32_t* a, const uint32_t* b) {
    asm volatile(
        "mma.sync.aligned.m16n8k8.row.col.f32.tf32.tf32.f32 "
        "{%0,%1,%2,%3}, {%4,%5,%6,%7}, {%8,%9}, {%0,%1,%2,%3};"
        : "+f"(c[0]), "+f"(c[1]), "+f"(c[2]), "+f"(c[3])
        : "r"(a[0]), "r"(a[1]), "r"(a[2]), "r"(a[3]), "r"(b[0]), "r"(b[1]));
}
__device__ __forceinline__ float sigmoidf_(float x) {
    return 1.0f / (1.0f + __expf(-x));
}

// ---------------------------------------------------------------------------
// Fused input GEMMs: z=0 -> sigmoid(emb@W_ih+b_h), z=1 -> emb@W1+b1,
// z=2 -> emb@W2+b2. M=8192, N=K=512. (FFMA path; small fraction of runtime.)
// ---------------------------------------------------------------------------
#define BM 128
#define BN 128
#define BK 16
#define TM 8
#define TN 8
#define PAD 4

__global__ __launch_bounds__(256) void gemm_embed3_k(
    const int*   __restrict__ tokens,
    const float* __restrict__ E,
    const float* __restrict__ W_ih, const float* __restrict__ b_h,
    const float* __restrict__ W1,   const float* __restrict__ b1,
    const float* __restrict__ W2,   const float* __restrict__ b2,
    float* __restrict__ fOut, float* __restrict__ a1Out, float* __restrict__ a2Out)
{
    __shared__ float As[BK][BM + PAD];
    __shared__ float Bs[BK][BN + PAD];

    const int z = blockIdx.z;
    const float* W    = (z == 0) ? W_ih : ((z == 1) ? W1 : W2);
    const float* bias = (z == 0) ? b_h  : ((z == 1) ? b1 : b2);
    float*       C    = (z == 0) ? fOut : ((z == 1) ? a1Out : a2Out);

    const int tid = threadIdx.x;
    const int m0  = blockIdx.y * BM;
    const int n0  = blockIdx.x * BN;

    const int rA = tid >> 2;
    const int cA = (tid & 3) << 2;
    const int rB = tid >> 5;
    const int cB = (tid & 31) << 2;
    const int tr = (tid >> 4) << 3;
    const int tc = (tid & 15) << 3;

    const int tok0 = tokens[m0 + rA];
    const int tok1 = tokens[m0 + rA + 64];
    const float* arow0 = E + (size_t)tok0 * Dd;
    const float* arow1 = E + (size_t)tok1 * Dd;

    float acc[TM][TN] = {};

    for (int k0 = 0; k0 < Dd; k0 += BK) {
        float4 a0 = *reinterpret_cast<const float4*>(arow0 + k0 + cA);
        float4 a1 = *reinterpret_cast<const float4*>(arow1 + k0 + cA);
        As[cA + 0][rA]      = a0.x;  As[cA + 1][rA]      = a0.y;
        As[cA + 2][rA]      = a0.z;  As[cA + 3][rA]      = a0.w;
        As[cA + 0][rA + 64] = a1.x;  As[cA + 1][rA + 64] = a1.y;
        As[cA + 2][rA + 64] = a1.z;  As[cA + 3][rA + 64] = a1.w;

        float4 b0v = *reinterpret_cast<const float4*>(W + (size_t)(k0 + rB)     * Dd + n0 + cB);
        float4 b1v = *reinterpret_cast<const float4*>(W + (size_t)(k0 + rB + 8) * Dd + n0 + cB);
        *reinterpret_cast<float4*>(&Bs[rB][cB])     = b0v;
        *reinterpret_cast<float4*>(&Bs[rB + 8][cB]) = b1v;

        __syncthreads();

        #pragma unroll
        for (int k = 0; k < BK; k++) {
            float regM[TM], regN[TN];
            *reinterpret_cast<float4*>(&regM[0]) = *reinterpret_cast<const float4*>(&As[k][tr]);
            *reinterpret_cast<float4*>(&regM[4]) = *reinterpret_cast<const float4*>(&As[k][tr + 4]);
            *reinterpret_cast<float4*>(&regN[0]) = *reinterpret_cast<const float4*>(&Bs[k][tc]);
            *reinterpret_cast<float4*>(&regN[4]) = *reinterpret_cast<const float4*>(&Bs[k][tc + 4]);
            #pragma unroll
            for (int i = 0; i < TM; i++)
                #pragma unroll
                for (int j = 0; j < TN; j++)
                    acc[i][j] = fmaf(regM[i], regN[j], acc[i][j]);
        }
        __syncthreads();
    }

    #pragma unroll
    for (int i = 0; i < TM; i++) {
        float* crow = C + (size_t)(m0 + tr + i) * Dd + n0 + tc;
        #pragma unroll
        for (int j = 0; j < TN; j++) {
            float v = acc[i][j] + bias[n0 + tc + j];
            if (z == 0) v = sigmoidf_(v);
            crow[j] = v;
        }
    }
}

// ---------------------------------------------------------------------------
// Logits GEMM via legacy tensor path: mma.sync.m16n8k8.tf32 (base-target PTX).
// C[m][n] = sum_k X[m][k]*E[n][k]. M=8192, N=32000, K=512.
// 128x128 CTA tile, BK=32, 3-stage cp.async pipeline, 8 warps of 64x32.
// Smem row stride = 36 floats -> all fragment LDS are bank-conflict-free.
// ---------------------------------------------------------------------------
#define LST 36                              // floats per smem row (32 + 4 pad)
#define SLAB_FLOATS (128 * LST)             // 4608 per operand
#define STAGE_FLOATS (2 * SLAB_FLOATS)      // A then B
#define STAGE_BYTES  (STAGE_FLOATS * 4)     // 36864
#define ABYTES       (SLAB_FLOATS * 4)      // 18432
#define LSM_TOTAL    (3 * STAGE_BYTES)      // 110592 B
#define NSLAB 16                            // 512 / 32

__global__ __launch_bounds__(256, 2) void gemm_logits_mma(
    const float* __restrict__ X,
    const float* __restrict__ E,
    float*       __restrict__ C)
{
    extern __shared__ float sm[];
    const int tid  = threadIdx.x;
    const int w    = tid >> 5;
    const int lane = tid & 31;
    const int grp  = lane >> 2;     // 0..7
    const int tig  = lane & 3;      // 0..3
    const int wm   = w & 1;         // 2 m-groups of 64
    const int wn   = w >> 1;        // 4 n-groups of 32
    const int m0   = blockIdx.y * 128;
    const int n0   = blockIdx.x * 128;

    const uint32_t sbase = smem_u32(sm);
    const float* Xr = X + (size_t)m0 * Dd;
    const float* Er = E + (size_t)n0 * Dd;

    float acc[4][4][4] = {};

    // issue one BK=32 slab (A 128x32 + B 128x32) via cp.async 16B
    auto issue = [&](int slab, int buf) {
        const int kb = slab * 32;
        const uint32_t stage = sbase + buf * STAGE_BYTES;
        #pragma unroll
        for (int i = 0; i < 4; i++) {
            int lin = tid + i * 256;
            int row = lin >> 3, c4 = lin & 7;
            asm volatile("cp.async.cg.shared.global [%0], [%1], 16;"
                :: "r"(stage + (uint32_t)(row * LST + c4 * 4) * 4),
                   "l"(Xr + (size_t)row * Dd + kb + c4 * 4) : "memory");
        }
        #pragma unroll
        for (int i = 0; i < 4; i++) {
            int lin = tid + i * 256;
            int row = lin >> 3, c4 = lin & 7;
            asm volatile("cp.async.cg.shared.global [%0], [%1], 16;"
                :: "r"(stage + ABYTES + (uint32_t)(row * LST + c4 * 4) * 4),
                   "l"(Er + (size_t)row * Dd + kb + c4 * 4) : "memory");
        }
    };

    // prologue: slabs 0 and 1
    issue(0, 0);
    asm volatile("cp.async.commit_group;" ::: "memory");
    issue(1, 1);
    asm volatile("cp.async.commit_group;" ::: "memory");

    #pragma unroll 1
    for (int t = 0; t < NSLAB; t++) {
        asm volatile("cp.async.wait_group 1;" ::: "memory");
        __syncthreads();

        if (t + 2 < NSLAB) issue(t + 2, (t + 2) % 3);
        asm volatile("cp.async.commit_group;" ::: "memory");

        const float* A_ = sm + (t % 3) * STAGE_FLOATS;
        const float* B_ = A_ + SLAB_FLOATS;

        #pragma unroll
        for (int ks = 0; ks < 4; ks++) {
            const int kk = ks * 8;
            uint32_t af[4][4], bf[4][2];
            #pragma unroll
            for (int mi = 0; mi < 4; mi++) {
                const int r = wm * 64 + mi * 16 + grp;
                af[mi][0] = f2tf32(A_[r * LST + kk + tig]);
                af[mi][1] = f2tf32(A_[(r + 8) * LST + kk + tig]);
                af[mi][2] = f2tf32(A_[r * LST + kk + tig + 4]);
                af[mi][3] = f2tf32(A_[(r + 8) * LST + kk + tig + 4]);
            }
            #pragma unroll
            for (int ni = 0; ni < 4; ni++) {
                const int n = wn * 32 + ni * 8 + grp;
                bf[ni][0] = f2tf32(B_[n * LST + kk + tig]);
                bf[ni][1] = f2tf32(B_[n * LST + kk + tig + 4]);
            }
            #pragma unroll
            for (int mi = 0; mi < 4; mi++)
                #pragma unroll
                for (int ni = 0; ni < 4; ni++)
                    mma_tf32(acc[mi][ni], af[mi], bf[ni]);
        }
    }

    // epilogue
    #pragma unroll
    for (int mi = 0; mi < 4; mi++) {
        const int r = m0 + wm * 64 + mi * 16 + grp;
        #pragma unroll
        for (int ni = 0; ni < 4; ni++) {
            const int cix = n0 + wn * 32 + ni * 8 + tig * 2;
            *reinterpret_cast<float2*>(C + (size_t)r * Vv + cix) =
                make_float2(acc[mi][ni][0], acc[mi][ni][1]);
            *reinterpret_cast<float2*>(C + (size_t)(r + 8) * Vv + cix) =
                make_float2(acc[mi][ni][2], acc[mi][ni][3]);
        }
    }
}

// ---------------------------------------------------------------------------
// xmix = silu(a1) * a2, in place over a1.
// ---------------------------------------------------------------------------
__global__ void mix_k(float4* __restrict__ a1, const float4* __restrict__ a2, int n4)
{
    int i = blockIdx.x * blockDim.x + threadIdx.x;
    if (i < n4) {
        float4 x = a1[i];
        float4 y = a2[i];
        x.x = x.x * sigmoidf_(x.x) * y.x;
        x.y = x.y * sigmoidf_(x.y) * y.y;
        x.z = x.z * sigmoidf_(x.z) * y.z;
        x.w = x.w * sigmoidf_(x.w) * y.w;
        a1[i] = x;
    }
}

// ---------------------------------------------------------------------------
// Sequential scan + both layernorms fused. One block per batch row.
// ---------------------------------------------------------------------------
__device__ __forceinline__ void block_red2(float& a, float& b, float* red, int tid)
{
    #pragma unroll
    for (int off = 16; off > 0; off >>= 1) {
        a += __shfl_xor_sync(0xffffffffu, a, off);
        b += __shfl_xor_sync(0xffffffffu, b, off);
    }
    const int w = tid >> 5;
    if ((tid & 31) == 0) { red[w] = a; red[8 + w] = b; }
    __syncthreads();
    a = red[0] + red[1] + red[2] + red[3];
    b = red[8] + red[9] + red[10] + red[11];
    __syncthreads();
}

__global__ __launch_bounds__(128) void scan_k(
    const float* __restrict__ f,
    const float* __restrict__ x,
    const float* __restrict__ ln_g,  const float* __restrict__ ln_b,
    const float* __restrict__ h0,
    const float* __restrict__ lnf_g, const float* __restrict__ lnf_b,
    float*       __restrict__ xf)
{
    const int b   = blockIdx.x;
    const int tid = threadIdx.x;
    __shared__ float red[16];

    const float4* fp = reinterpret_cast<const float4*>(f  + (size_t)b * Ss * Dd);
    const float4* xp = reinterpret_cast<const float4*>(x  + (size_t)b * Ss * Dd);
    float4*       op = reinterpret_cast<float4*>      (xf + (size_t)b * Ss * Dd);

    const float4 g  = reinterpret_cast<const float4*>(ln_g)[tid];
    const float4 be = reinterpret_cast<const float4*>(ln_b)[tid];
    const float4 fg = reinterpret_cast<const float4*>(lnf_g)[tid];
    const float4 fb = reinterpret_cast<const float4*>(lnf_b)[tid];
    float4 h        = reinterpret_cast<const float4*>(h0)[tid];

    const float invD = 1.0f / (float)Dd;

    for (int s = 0; s < Ss; s++) {
        float4 ft = fp[s * 128 + tid];
        float4 xt = xp[s * 128 + tid];

        float4 hr;
        hr.x = ft.x * h.x + (1.0f - ft.x) * xt.x;
        hr.y = ft.y * h.y + (1.0f - ft.y) * xt.y;
        hr.z = ft.z * h.z + (1.0f - ft.z) * xt.z;
        hr.w = ft.w * h.w + (1.0f - ft.w) * xt.w;

        float sa = hr.x + hr.y + hr.z + hr.w;
        float sb = hr.x * hr.x + hr.y * hr.y + hr.z * hr.z + hr.w * hr.w;
        block_red2(sa, sb, red, tid);
        float mean = sa * invD;
        float var  = sb * invD - mean * mean;
        float rstd = rsqrtf(var + EPSF);

        float4 hn;
        hn.x = (hr.x - mean) * rstd * g.x + be.x + h.x;
        hn.y = (hr.y - mean) * rstd * g.y + be.y + h.y;
        hn.z = (hr.z - mean) * rstd * g.z + be.z + h.z;
        hn.w = (hr.w - mean) * rstd * g.w + be.w + h.w;
        h = hn;

        sa = hn.x + hn.y + hn.z + hn.w;
        sb = hn.x * hn.x + hn.y * hn.y + hn.z * hn.z + hn.w * hn.w;
        block_red2(sa, sb, red, tid);
        mean = sa * invD;
        var  = sb * invD - mean * mean;
        rstd = rsqrtf(var + EPSF);

        float4 o;
        o.x = (hn.x - mean) * rstd * fg.x + fb.x;
        o.y = (hn.y - mean) * rstd * fg.y + fb.y;
        o.z = (hn.z - mean) * rstd * fg.z + fb.z;
        o.w = (hn.w - mean) * rstd * fg.w + fb.w;
        op[s * 128 + tid] = o;
    }
}

// ---------------------------------------------------------------------------
extern "C" void kernel_launch(void* const* d_in, const int* in_sizes, int n_in,
                              void* d_out, int out_size)
{
    const int*   tokens = (const int*)  d_in[0];
    const float* E      = (const float*)d_in[1];
    const float* W_ih   = (const float*)d_in[2];
    const float* b_h    = (const float*)d_in[3];
    const float* W1     = (const float*)d_in[4];
    const float* b1     = (const float*)d_in[5];
    const float* W2     = (const float*)d_in[6];
    const float* b2     = (const float*)d_in[7];
    const float* ln_g   = (const float*)d_in[8];
    const float* ln_b   = (const float*)d_in[9];
    const float* h0     = (const float*)d_in[10];
    const float* lnf_g  = (const float*)d_in[11];
    const float* lnf_b  = (const float*)d_in[12];
    float* out          = (float*)d_out;

    float *fP, *a1P, *a2P, *xfP;
    cudaGetSymbolAddress((void**)&fP,  g_f);
    cudaGetSymbolAddress((void**)&a1P, g_a1);
    cudaGetSymbolAddress((void**)&a2P, g_a2);
    cudaGetSymbolAddress((void**)&xfP, g_xf);

    cudaFuncSetAttribute(gemm_logits_mma, cudaFuncAttributeMaxDynamicSharedMemorySize,
                         LSM_TOTAL);

    gemm_embed3_k<<<dim3(Dd / BN, MT / BM, 3), 256>>>(
        tokens, E, W_ih, b_h, W1, b1, W2, b2, fP, a1P, a2P);

    const int n4 = MT * Dd / 4;
    mix_k<<<(n4 + 255) / 256, 256>>>((float4*)a1P, (const float4*)a2P, n4);

    scan_k<<<Bb, 128>>>(fP, a1P, ln_g, ln_b, h0, lnf_g, lnf_b, xfP);

    gemm_logits_mma<<<dim3(Vv / 128, MT / 128), 256, LSM_TOTAL>>>(xfP, E, out);
}